// round 1
// baseline (speedup 1.0000x reference)
#include <cuda_runtime.h>

#define BB   2
#define SS   2048
#define HIDD 1024
#define NHH  4
#define HDD  256

// Scratch (allocation-free rule -> __device__ globals)
__device__ float g_q[BB*NHH*SS*HDD];
__device__ float g_k[BB*NHH*SS*HDD];
__device__ float g_v[BB*NHH*SS*HDD];
__device__ float g_o[BB*SS*HIDD];

// ---------------------------------------------------------------------------
// Kernel 1: QKV GEMM (C = hidden @ W_qkv^T) fused with RoPE on Q,K.
// 128x128x16 tiles, 256 threads, 8x8 micro-tile per thread.
// ---------------------------------------------------------------------------
__global__ __launch_bounds__(256) void qkv_gemm_kernel(
    const float* __restrict__ A,    // [4096][1024]
    const float* __restrict__ W,    // [3072][1024]
    const float* __restrict__ fr,   // [2048][128]
    const float* __restrict__ fi)   // [2048][128]
{
    __shared__ float As[16][128];
    __shared__ float Bs[16][128];
    const int tid = threadIdx.x;
    const int m0 = blockIdx.y * 128;
    const int n0 = blockIdx.x * 128;

    float acc[8][8];
#pragma unroll
    for (int i = 0; i < 8; i++)
#pragma unroll
        for (int j = 0; j < 8; j++) acc[i][j] = 0.f;

    const int ty = tid >> 4, tx = tid & 15;
    const int lr = tid >> 2;           // 0..63
    const int lc = (tid & 3) << 2;     // 0,4,8,12

    for (int k0 = 0; k0 < 1024; k0 += 16) {
#pragma unroll
        for (int i = 0; i < 2; i++) {
            int row = lr + i * 64;
            float4 va = *(const float4*)&A[(size_t)(m0 + row) * 1024 + k0 + lc];
            As[lc + 0][row] = va.x; As[lc + 1][row] = va.y;
            As[lc + 2][row] = va.z; As[lc + 3][row] = va.w;
            float4 vb = *(const float4*)&W[(size_t)(n0 + row) * 1024 + k0 + lc];
            Bs[lc + 0][row] = vb.x; Bs[lc + 1][row] = vb.y;
            Bs[lc + 2][row] = vb.z; Bs[lc + 3][row] = vb.w;
        }
        __syncthreads();
#pragma unroll
        for (int kk = 0; kk < 16; kk++) {
            float a[8], bq[8];
#pragma unroll
            for (int i = 0; i < 8; i++) a[i] = As[kk][ty * 8 + i];
#pragma unroll
            for (int j = 0; j < 8; j++) bq[j] = Bs[kk][tx * 8 + j];
#pragma unroll
            for (int i = 0; i < 8; i++)
#pragma unroll
                for (int j = 0; j < 8; j++) acc[i][j] += a[i] * bq[j];
        }
        __syncthreads();
    }

    // Epilogue: apply RoPE to q,k; scatter to [B][NH][S][HD] buffers.
#pragma unroll
    for (int i = 0; i < 8; i++) {
        int m  = m0 + ty * 8 + i;
        int bb = m >> 11;          // / 2048
        int ss = m & 2047;
#pragma unroll
        for (int j = 0; j < 8; j += 2) {
            int n     = n0 + tx * 8 + j;
            int which = n >> 10;           // 0=q 1=k 2=v
            int rem   = n & 1023;
            int h     = rem >> 8;
            int d     = rem & 255;
            size_t oidx = (((size_t)(bb * NHH + h)) * SS + ss) * HDD + d;
            if (which == 2) {
                g_v[oidx]     = acc[i][j];
                g_v[oidx + 1] = acc[i][j + 1];
            } else {
                float fre = fr[ss * (HDD / 2) + (d >> 1)];
                float fim = fi[ss * (HDD / 2) + (d >> 1)];
                float re = acc[i][j], im = acc[i][j + 1];
                float o0 = re * fre - im * fim;
                float o1 = re * fim + im * fre;
                if (which == 0) { g_q[oidx] = o0; g_q[oidx + 1] = o1; }
                else            { g_k[oidx] = o0; g_k[oidx + 1] = o1; }
            }
        }
    }
}

// ---------------------------------------------------------------------------
// Kernel 2: causal flash attention. One CTA per (64 q-rows, head, batch).
// K/V tiles 64x256 in dynamic smem, online softmax, O in registers.
// ---------------------------------------------------------------------------
#define QSTR 264   // 256 + 8 pad (keeps 16B alignment, reduces bank conflicts)
#define PSTR 65

extern __shared__ float asmem[];

__global__ __launch_bounds__(256) void attn_kernel(
    const float* __restrict__ qg, const float* __restrict__ kg,
    const float* __restrict__ vg, float* __restrict__ og)
{
    float* Qs = asmem;                  // [64][QSTR]
    float* Ks = Qs + 64 * QSTR;
    float* Vs = Ks + 64 * QSTR;
    float* Ps = Vs + 64 * QSTR;         // [64][PSTR]
    float* mS = Ps + 64 * PSTR;         // [64]
    float* lS = mS + 64;                // [64]
    float* rS = lS + 64;                // [64]

    const int tid = threadIdx.x;
    const int q0  = blockIdx.x * 64;
    const int h   = blockIdx.y;
    const int b   = blockIdx.z;
    const size_t base = ((size_t)(b * NHH + h)) * SS * HDD;

    const float scale = 0.0625f;  // 256^-0.5

    // load Q (scaled)
    for (int i = tid; i < 64 * 64; i += 256) {
        int row = i >> 6, c4 = (i & 63) << 2;
        float4 v = *(const float4*)&qg[base + (size_t)(q0 + row) * HDD + c4];
        float4 w = make_float4(v.x * scale, v.y * scale, v.z * scale, v.w * scale);
        *(float4*)&Qs[row * QSTR + c4] = w;
    }
    if (tid < 64) { mS[tid] = -1e30f; lS[tid] = 0.f; }

    float o[64];
#pragma unroll
    for (int i = 0; i < 64; i++) o[i] = 0.f;

    const int r0  = (tid >> 4) * 4;     // S rows (4)
    const int c0  = (tid & 15) * 4;     // S cols (4)
    const int rp  = tid >> 2;           // PV row
    const int cp0 = (tid & 3) * 64;     // PV col chunk

    const int nkb = (q0 >> 6) + 1;      // causal tiles only
    for (int kbi = 0; kbi < nkb; kbi++) {
        const int k0 = kbi * 64;
        __syncthreads();   // prev PV done before overwriting tiles
        for (int i = tid; i < 64 * 64; i += 256) {
            int row = i >> 6, c4 = (i & 63) << 2;
            size_t gi = base + (size_t)(k0 + row) * HDD + c4;
            *(float4*)&Ks[row * QSTR + c4] = *(const float4*)&kg[gi];
            *(float4*)&Vs[row * QSTR + c4] = *(const float4*)&vg[gi];
        }
        __syncthreads();

        // S = Q K^T  (4x4 micro-tile per thread)
        float sacc[4][4];
#pragma unroll
        for (int i = 0; i < 4; i++)
#pragma unroll
            for (int j = 0; j < 4; j++) sacc[i][j] = 0.f;

        for (int k = 0; k < HDD; k += 4) {
            float4 qv[4], kv[4];
#pragma unroll
            for (int i = 0; i < 4; i++) qv[i] = *(const float4*)&Qs[(r0 + i) * QSTR + k];
#pragma unroll
            for (int j = 0; j < 4; j++) kv[j] = *(const float4*)&Ks[(c0 + j) * QSTR + k];
#pragma unroll
            for (int i = 0; i < 4; i++)
#pragma unroll
                for (int j = 0; j < 4; j++)
                    sacc[i][j] += qv[i].x * kv[j].x + qv[i].y * kv[j].y +
                                  qv[i].z * kv[j].z + qv[i].w * kv[j].w;
        }
#pragma unroll
        for (int i = 0; i < 4; i++)
#pragma unroll
            for (int j = 0; j < 4; j++)
                Ps[(r0 + i) * PSTR + c0 + j] = sacc[i][j];
        __syncthreads();

        // online softmax: one thread per row
        if (tid < 64) {
            int r  = tid;
            int qi = q0 + r;
            float mold = mS[r];
            float mt = mold;
            for (int j = 0; j < 64; j++)
                if (k0 + j <= qi) mt = fmaxf(mt, Ps[r * PSTR + j]);
            float resc = __expf(mold - mt);
            float sum = 0.f;
            for (int j = 0; j < 64; j++) {
                float p = (k0 + j <= qi) ? __expf(Ps[r * PSTR + j] - mt) : 0.f;
                Ps[r * PSTR + j] = p;
                sum += p;
            }
            lS[r] = lS[r] * resc + sum;
            mS[r] = mt;
            rS[r] = resc;
        }
        __syncthreads();

        // O = O*resc + P V
        float resc = rS[rp];
#pragma unroll
        for (int i = 0; i < 64; i++) o[i] *= resc;
        for (int j = 0; j < 64; j++) {
            float p = Ps[rp * PSTR + j];
            const float* vrow = &Vs[j * QSTR + cp0];
#pragma unroll
            for (int c = 0; c < 64; c += 4) {
                float4 vv = *(const float4*)&vrow[c];
                o[c + 0] += p * vv.x; o[c + 1] += p * vv.y;
                o[c + 2] += p * vv.z; o[c + 3] += p * vv.w;
            }
        }
    }

    float linv = 1.f / lS[rp];
    size_t ob = ((size_t)b * SS + (q0 + rp)) * HIDD + h * HDD + cp0;
#pragma unroll
    for (int c = 0; c < 64; c += 4) {
        float4 w = make_float4(o[c] * linv, o[c + 1] * linv,
                               o[c + 2] * linv, o[c + 3] * linv);
        *(float4*)&og[ob + c] = w;
    }
}

// ---------------------------------------------------------------------------
// Kernel 3: output GEMM  out = attn @ W_o^T  (4096x1024x1024)
// ---------------------------------------------------------------------------
__global__ __launch_bounds__(256) void o_gemm_kernel(
    const float* __restrict__ A,    // [4096][1024]
    const float* __restrict__ W,    // [1024][1024]
    float* __restrict__ C)          // [4096][1024]
{
    __shared__ float As[16][128];
    __shared__ float Bs[16][128];
    const int tid = threadIdx.x;
    const int m0 = blockIdx.y * 128;
    const int n0 = blockIdx.x * 128;

    float acc[8][8];
#pragma unroll
    for (int i = 0; i < 8; i++)
#pragma unroll
        for (int j = 0; j < 8; j++) acc[i][j] = 0.f;

    const int ty = tid >> 4, tx = tid & 15;
    const int lr = tid >> 2;
    const int lc = (tid & 3) << 2;

    for (int k0 = 0; k0 < 1024; k0 += 16) {
#pragma unroll
        for (int i = 0; i < 2; i++) {
            int row = lr + i * 64;
            float4 va = *(const float4*)&A[(size_t)(m0 + row) * 1024 + k0 + lc];
            As[lc + 0][row] = va.x; As[lc + 1][row] = va.y;
            As[lc + 2][row] = va.z; As[lc + 3][row] = va.w;
            float4 vb = *(const float4*)&W[(size_t)(n0 + row) * 1024 + k0 + lc];
            Bs[lc + 0][row] = vb.x; Bs[lc + 1][row] = vb.y;
            Bs[lc + 2][row] = vb.z; Bs[lc + 3][row] = vb.w;
        }
        __syncthreads();
#pragma unroll
        for (int kk = 0; kk < 16; kk++) {
            float a[8], bq[8];
#pragma unroll
            for (int i = 0; i < 8; i++) a[i] = As[kk][ty * 8 + i];
#pragma unroll
            for (int j = 0; j < 8; j++) bq[j] = Bs[kk][tx * 8 + j];
#pragma unroll
            for (int i = 0; i < 8; i++)
#pragma unroll
                for (int j = 0; j < 8; j++) acc[i][j] += a[i] * bq[j];
        }
        __syncthreads();
    }

#pragma unroll
    for (int i = 0; i < 8; i++) {
        size_t rb = (size_t)(m0 + ty * 8 + i) * 1024 + n0 + tx * 8;
        float4 w0 = make_float4(acc[i][0], acc[i][1], acc[i][2], acc[i][3]);
        float4 w1 = make_float4(acc[i][4], acc[i][5], acc[i][6], acc[i][7]);
        *(float4*)&C[rb]     = w0;
        *(float4*)&C[rb + 4] = w1;
    }
}

// ---------------------------------------------------------------------------
extern "C" void kernel_launch(void* const* d_in, const int* in_sizes, int n_in,
                              void* d_out, int out_size)
{
    const float* hidden = (const float*)d_in[0];
    const float* fr     = (const float*)d_in[1];
    const float* fi     = (const float*)d_in[2];
    // d_in[3] = mask (unused: causal mask applied analytically, exactly matches -1e9 behavior)
    const float* Wqkv   = (const float*)d_in[4];
    const float* Wo     = (const float*)d_in[5];
    float* out = (float*)d_out;

    float *qb, *kb, *vb, *ob;
    cudaGetSymbolAddress((void**)&qb, g_q);
    cudaGetSymbolAddress((void**)&kb, g_k);
    cudaGetSymbolAddress((void**)&vb, g_v);
    cudaGetSymbolAddress((void**)&ob, g_o);

    // 1) QKV + RoPE
    dim3 g1(3072 / 128, 4096 / 128);
    qkv_gemm_kernel<<<g1, 256>>>(hidden, Wqkv, fr, fi);

    // 2) flash attention
    const int smem = (3 * 64 * QSTR + 64 * PSTR + 192) * (int)sizeof(float);
    cudaFuncSetAttribute(attn_kernel, cudaFuncAttributeMaxDynamicSharedMemorySize, smem);
    dim3 g2(SS / 64, NHH, BB);
    attn_kernel<<<g2, 256, smem>>>(qb, kb, vb, ob);

    // 3) output projection
    dim3 g3(1024 / 128, 4096 / 128);
    o_gemm_kernel<<<g3, 256>>>(ob, Wo, out);
}

// round 2
// speedup vs baseline: 3.2159x; 3.2159x over previous
#include <cuda_runtime.h>

#define BB   2
#define SS   2048
#define HIDD 1024
#define NHH  4
#define HDD  256

// Scratch (allocation-free rule -> __device__ globals)
__device__ float g_q[BB*NHH*SS*HDD];
__device__ float g_k[BB*NHH*SS*HDD];
__device__ float g_v[BB*NHH*SS*HDD];
__device__ float g_o[BB*SS*HIDD];

// ---------------------------------------------------------------------------
// Kernel 1: QKV GEMM (C = hidden @ W_qkv^T) fused with RoPE on Q,K.
// ---------------------------------------------------------------------------
__global__ __launch_bounds__(256) void qkv_gemm_kernel(
    const float* __restrict__ A,    // [4096][1024]
    const float* __restrict__ W,    // [3072][1024]
    const float* __restrict__ fr,   // [2048][128]
    const float* __restrict__ fi)   // [2048][128]
{
    __shared__ float As[16][128];
    __shared__ float Bs[16][128];
    const int tid = threadIdx.x;
    const int m0 = blockIdx.y * 128;
    const int n0 = blockIdx.x * 128;

    float acc[8][8];
#pragma unroll
    for (int i = 0; i < 8; i++)
#pragma unroll
        for (int j = 0; j < 8; j++) acc[i][j] = 0.f;

    const int ty = tid >> 4, tx = tid & 15;
    const int lr = tid >> 2;
    const int lc = (tid & 3) << 2;

    for (int k0 = 0; k0 < 1024; k0 += 16) {
#pragma unroll
        for (int i = 0; i < 2; i++) {
            int row = lr + i * 64;
            float4 va = *(const float4*)&A[(size_t)(m0 + row) * 1024 + k0 + lc];
            As[lc + 0][row] = va.x; As[lc + 1][row] = va.y;
            As[lc + 2][row] = va.z; As[lc + 3][row] = va.w;
            float4 vb = *(const float4*)&W[(size_t)(n0 + row) * 1024 + k0 + lc];
            Bs[lc + 0][row] = vb.x; Bs[lc + 1][row] = vb.y;
            Bs[lc + 2][row] = vb.z; Bs[lc + 3][row] = vb.w;
        }
        __syncthreads();
#pragma unroll
        for (int kk = 0; kk < 16; kk++) {
            float a[8], bq[8];
#pragma unroll
            for (int i = 0; i < 8; i++) a[i] = As[kk][ty * 8 + i];
#pragma unroll
            for (int j = 0; j < 8; j++) bq[j] = Bs[kk][tx * 8 + j];
#pragma unroll
            for (int i = 0; i < 8; i++)
#pragma unroll
                for (int j = 0; j < 8; j++) acc[i][j] += a[i] * bq[j];
        }
        __syncthreads();
    }

#pragma unroll
    for (int i = 0; i < 8; i++) {
        int m  = m0 + ty * 8 + i;
        int bb = m >> 11;
        int ss = m & 2047;
#pragma unroll
        for (int j = 0; j < 8; j += 2) {
            int n     = n0 + tx * 8 + j;
            int which = n >> 10;           // 0=q 1=k 2=v
            int rem   = n & 1023;
            int h     = rem >> 8;
            int d     = rem & 255;
            size_t oidx = (((size_t)(bb * NHH + h)) * SS + ss) * HDD + d;
            if (which == 2) {
                g_v[oidx]     = acc[i][j];
                g_v[oidx + 1] = acc[i][j + 1];
            } else {
                float fre = fr[ss * (HDD / 2) + (d >> 1)];
                float fim = fi[ss * (HDD / 2) + (d >> 1)];
                float re = acc[i][j], im = acc[i][j + 1];
                float o0 = re * fre - im * fim;
                float o1 = re * fim + im * fre;
                if (which == 0) { g_q[oidx] = o0; g_q[oidx + 1] = o1; }
                else            { g_k[oidx] = o0; g_k[oidx + 1] = o1; }
            }
        }
    }
}

// ---------------------------------------------------------------------------
// Kernel 2: causal flash attention, rewritten.
//   Q,K stored k-major (transposed) in smem with stride 68 floats (272B,
//   16B aligned) -> S-phase lane loads are contiguous float4 (no conflicts).
//   V row-major stride 256 (lanes contiguous).
//   Softmax in registers via shfl-xor over 16-lane row groups.
//   PV: 8 rows x (4+4) cols per thread, broadcast P loads.
// ---------------------------------------------------------------------------
#define KSTR 68
#define PSTR 65

extern __shared__ float asmem[];

__global__ __launch_bounds__(256, 1) void attn_kernel(
    const float* __restrict__ qg, const float* __restrict__ kg,
    const float* __restrict__ vg, float* __restrict__ og)
{
    float* Qt = asmem;                 // [256][KSTR]  k-major
    float* Kt = Qt + 256 * KSTR;       // [256][KSTR]  k-major
    float* Vs = Kt + 256 * KSTR;       // [64][256]    row-major
    float* Ps = Vs + 64 * 256;         // [64][PSTR]
    float* rS = Ps + 64 * PSTR;        // [64] rescale factors
    float* lS = rS + 64;               // [64] final 1/l

    const int tid = threadIdx.x;
    const int nq  = gridDim.x;
    const int qt  = nq - 1 - blockIdx.x;    // heavy CTAs first
    const int q0  = qt * 64;
    const int h   = blockIdx.y;
    const int b   = blockIdx.z;
    const size_t base = ((size_t)(b * NHH + h)) * SS * HDD;
    const float scale = 0.0625f;

    // load Q transposed + scaled: lane = k (coalesced LDG), row = iter
    {
        const float* qrow = qg + base + (size_t)q0 * HDD + tid;
        float* qdst = Qt + tid * KSTR;
#pragma unroll 4
        for (int r = 0; r < 64; r++)
            qdst[r] = qrow[(size_t)r * HDD] * scale;
    }

    // S-phase mapping: rows r0..r0+3, cols c0..c0+3
    const int r0 = (tid >> 4) * 4;
    const int c0 = (tid & 15) * 4;
    // PV mapping: rows rp0..rp0+7, col chunks cpA..+3 and cpA+128..+3... (x2 float4)
    const int rp0 = (tid >> 5) * 8;
    const int cpA = (tid & 31) * 4;     // first 4-col chunk; second at +128

    float mrun[4], lrun[4];
#pragma unroll
    for (int i = 0; i < 4; i++) { mrun[i] = -1e30f; lrun[i] = 0.f; }

    float o[8][8];   // [row][0..3 -> cpA, 4..7 -> cpA+128]
#pragma unroll
    for (int i = 0; i < 8; i++)
#pragma unroll
        for (int c = 0; c < 8; c++) o[i][c] = 0.f;

    const int nkb = qt + 1;
    for (int kbi = 0; kbi < nkb; kbi++) {
        const int k0 = kbi * 64;
        __syncthreads();   // prev PV done before overwriting K/V

        // K transposed: lane = k, scalar stores (4-way bank conflict, cheap)
        {
            const float* krow = kg + base + (size_t)k0 * HDD + tid;
            float* kdst = Kt + tid * KSTR;
#pragma unroll 4
            for (int r = 0; r < 64; r++)
                kdst[r] = krow[(size_t)r * HDD];
        }
        // V row-major: float4 copies, lanes contiguous
        {
            int r = tid >> 2, c4 = (tid & 3) * 4;
#pragma unroll
            for (int it = 0; it < 16; it++) {
                *(float4*)&Vs[r * 256 + c4 + it * 16] =
                    *(const float4*)&vg[base + (size_t)(k0 + r) * HDD + c4 + it * 16];
            }
        }
        __syncthreads();

        // ---- S = Q K^T (4x4 per thread) ----
        float sacc[4][4];
#pragma unroll
        for (int i = 0; i < 4; i++)
#pragma unroll
            for (int j = 0; j < 4; j++) sacc[i][j] = 0.f;

#pragma unroll 4
        for (int kk = 0; kk < 256; kk++) {
            float4 a  = *(const float4*)&Qt[kk * KSTR + r0];
            float4 bq = *(const float4*)&Kt[kk * KSTR + c0];
            sacc[0][0] += a.x * bq.x; sacc[0][1] += a.x * bq.y;
            sacc[0][2] += a.x * bq.z; sacc[0][3] += a.x * bq.w;
            sacc[1][0] += a.y * bq.x; sacc[1][1] += a.y * bq.y;
            sacc[1][2] += a.y * bq.z; sacc[1][3] += a.y * bq.w;
            sacc[2][0] += a.z * bq.x; sacc[2][1] += a.z * bq.y;
            sacc[2][2] += a.z * bq.z; sacc[2][3] += a.z * bq.w;
            sacc[3][0] += a.w * bq.x; sacc[3][1] += a.w * bq.y;
            sacc[3][2] += a.w * bq.z; sacc[3][3] += a.w * bq.w;
        }

        // ---- online softmax in registers (16-lane row groups) ----
        float resc[4];
#pragma unroll
        for (int i = 0; i < 4; i++) {
            int qi = q0 + r0 + i;
            float mx = -1e30f;
#pragma unroll
            for (int j = 0; j < 4; j++) {
                if (k0 + c0 + j > qi) sacc[i][j] = -1e30f;
                mx = fmaxf(mx, sacc[i][j]);
            }
            mx = fmaxf(mx, __shfl_xor_sync(0xffffffffu, mx, 1));
            mx = fmaxf(mx, __shfl_xor_sync(0xffffffffu, mx, 2));
            mx = fmaxf(mx, __shfl_xor_sync(0xffffffffu, mx, 4));
            mx = fmaxf(mx, __shfl_xor_sync(0xffffffffu, mx, 8));
            float mnew = fmaxf(mrun[i], mx);
            resc[i] = __expf(mrun[i] - mnew);
            float sum = 0.f;
#pragma unroll
            for (int j = 0; j < 4; j++) {
                float p = __expf(sacc[i][j] - mnew);
                Ps[(r0 + i) * PSTR + c0 + j] = p;
                sum += p;
            }
            sum += __shfl_xor_sync(0xffffffffu, sum, 1);
            sum += __shfl_xor_sync(0xffffffffu, sum, 2);
            sum += __shfl_xor_sync(0xffffffffu, sum, 4);
            sum += __shfl_xor_sync(0xffffffffu, sum, 8);
            lrun[i] = lrun[i] * resc[i] + sum;
            mrun[i] = mnew;
        }
        if ((tid & 15) == 0) {
#pragma unroll
            for (int i = 0; i < 4; i++) rS[r0 + i] = resc[i];
        }
        __syncthreads();

        // ---- O = O*resc + P V ----
        float rr[8];
#pragma unroll
        for (int i = 0; i < 8; i++) rr[i] = rS[rp0 + i];
#pragma unroll
        for (int i = 0; i < 8; i++)
#pragma unroll
            for (int c = 0; c < 8; c++) o[i][c] *= rr[i];

#pragma unroll 2
        for (int j = 0; j < 64; j++) {
            float4 v0 = *(const float4*)&Vs[j * 256 + cpA];
            float4 v1 = *(const float4*)&Vs[j * 256 + cpA + 128];
#pragma unroll
            for (int i = 0; i < 8; i++) {
                float p = Ps[(rp0 + i) * PSTR + j];
                o[i][0] += p * v0.x; o[i][1] += p * v0.y;
                o[i][2] += p * v0.z; o[i][3] += p * v0.w;
                o[i][4] += p * v1.x; o[i][5] += p * v1.y;
                o[i][6] += p * v1.z; o[i][7] += p * v1.w;
            }
        }
    }

    // final normalization
    if ((tid & 15) == 0) {
#pragma unroll
        for (int i = 0; i < 4; i++) lS[r0 + i] = 1.f / lrun[i];
    }
    __syncthreads();

#pragma unroll
    for (int i = 0; i < 8; i++) {
        float linv = lS[rp0 + i];
        size_t ob = ((size_t)b * SS + (q0 + rp0 + i)) * HIDD + h * HDD;
        float4 w0 = make_float4(o[i][0] * linv, o[i][1] * linv,
                                o[i][2] * linv, o[i][3] * linv);
        float4 w1 = make_float4(o[i][4] * linv, o[i][5] * linv,
                                o[i][6] * linv, o[i][7] * linv);
        *(float4*)&og[ob + cpA]       = w0;
        *(float4*)&og[ob + cpA + 128] = w1;
    }
}

// ---------------------------------------------------------------------------
// Kernel 3: output GEMM  out = attn @ W_o^T  (4096x1024x1024)
// ---------------------------------------------------------------------------
__global__ __launch_bounds__(256) void o_gemm_kernel(
    const float* __restrict__ A,
    const float* __restrict__ W,
    float* __restrict__ C)
{
    __shared__ float As[16][128];
    __shared__ float Bs[16][128];
    const int tid = threadIdx.x;
    const int m0 = blockIdx.y * 128;
    const int n0 = blockIdx.x * 128;

    float acc[8][8];
#pragma unroll
    for (int i = 0; i < 8; i++)
#pragma unroll
        for (int j = 0; j < 8; j++) acc[i][j] = 0.f;

    const int ty = tid >> 4, tx = tid & 15;
    const int lr = tid >> 2;
    const int lc = (tid & 3) << 2;

    for (int k0 = 0; k0 < 1024; k0 += 16) {
#pragma unroll
        for (int i = 0; i < 2; i++) {
            int row = lr + i * 64;
            float4 va = *(const float4*)&A[(size_t)(m0 + row) * 1024 + k0 + lc];
            As[lc + 0][row] = va.x; As[lc + 1][row] = va.y;
            As[lc + 2][row] = va.z; As[lc + 3][row] = va.w;
            float4 vb = *(const float4*)&W[(size_t)(n0 + row) * 1024 + k0 + lc];
            Bs[lc + 0][row] = vb.x; Bs[lc + 1][row] = vb.y;
            Bs[lc + 2][row] = vb.z; Bs[lc + 3][row] = vb.w;
        }
        __syncthreads();
#pragma unroll
        for (int kk = 0; kk < 16; kk++) {
            float a[8], bq[8];
#pragma unroll
            for (int i = 0; i < 8; i++) a[i] = As[kk][ty * 8 + i];
#pragma unroll
            for (int j = 0; j < 8; j++) bq[j] = Bs[kk][tx * 8 + j];
#pragma unroll
            for (int i = 0; i < 8; i++)
#pragma unroll
                for (int j = 0; j < 8; j++) acc[i][j] += a[i] * bq[j];
        }
        __syncthreads();
    }

#pragma unroll
    for (int i = 0; i < 8; i++) {
        size_t rb = (size_t)(m0 + ty * 8 + i) * 1024 + n0 + tx * 8;
        float4 w0 = make_float4(acc[i][0], acc[i][1], acc[i][2], acc[i][3]);
        float4 w1 = make_float4(acc[i][4], acc[i][5], acc[i][6], acc[i][7]);
        *(float4*)&C[rb]     = w0;
        *(float4*)&C[rb + 4] = w1;
    }
}

// ---------------------------------------------------------------------------
extern "C" void kernel_launch(void* const* d_in, const int* in_sizes, int n_in,
                              void* d_out, int out_size)
{
    const float* hidden = (const float*)d_in[0];
    const float* fr     = (const float*)d_in[1];
    const float* fi     = (const float*)d_in[2];
    // d_in[3] = mask (causal handled analytically)
    const float* Wqkv   = (const float*)d_in[4];
    const float* Wo     = (const float*)d_in[5];
    float* out = (float*)d_out;

    float *qb, *kb, *vb, *ob;
    cudaGetSymbolAddress((void**)&qb, g_q);
    cudaGetSymbolAddress((void**)&kb, g_k);
    cudaGetSymbolAddress((void**)&vb, g_v);
    cudaGetSymbolAddress((void**)&ob, g_o);

    // 1) QKV + RoPE
    dim3 g1(3072 / 128, 4096 / 128);
    qkv_gemm_kernel<<<g1, 256>>>(hidden, Wqkv, fr, fi);

    // 2) flash attention
    const int smem = (2 * 256 * KSTR + 64 * 256 + 64 * PSTR + 128) * (int)sizeof(float);
    cudaFuncSetAttribute(attn_kernel, cudaFuncAttributeMaxDynamicSharedMemorySize, smem);
    dim3 g2(SS / 64, NHH, BB);
    attn_kernel<<<g2, 256, smem>>>(qb, kb, vb, ob);

    // 3) output projection
    dim3 g3(1024 / 128, 4096 / 128);
    o_gemm_kernel<<<g3, 256>>>(ob, Wo, out);
}

// round 4
// speedup vs baseline: 4.6507x; 1.4462x over previous
#include <cuda_runtime.h>
#include <cstdint>

#define BB   2
#define SS   2048
#define HIDD 1024
#define NHH  4
#define HDD  256

// Scratch (allocation-free rule -> __device__ globals)
__device__ float g_q[BB*NHH*SS*HDD];
__device__ float g_k[BB*NHH*SS*HDD];
__device__ float g_v[BB*NHH*SS*HDD];
__device__ float g_o[BB*SS*HIDD];

// ---------------------------------------------------------------------------
// tf32 mma.sync helpers (base PTX ISA, works on sm_103 target)
// ---------------------------------------------------------------------------
__device__ __forceinline__ void mma168(float* c, const uint32_t* a, const uint32_t* b) {
    asm volatile(
        "mma.sync.aligned.m16n8k8.row.col.f32.tf32.tf32.f32 "
        "{%0,%1,%2,%3}, {%4,%5,%6,%7}, {%8,%9}, {%0,%1,%2,%3};"
        : "+f"(c[0]), "+f"(c[1]), "+f"(c[2]), "+f"(c[3])
        : "r"(a[0]), "r"(a[1]), "r"(a[2]), "r"(a[3]), "r"(b[0]), "r"(b[1]));
}
__device__ __forceinline__ uint32_t f2tf32(float x) {
    uint32_t u;
    asm("cvt.rna.tf32.f32 %0, %1;" : "=r"(u) : "f"(x));
    return u;
}

// SMEM tile: [128 rows][36 words] (pad 4 -> conflict-free frag loads)
#define TSTR 36

// ---------------------------------------------------------------------------
// Shared mainloop: accumulates C(128x128) = A_tile @ B_tile^T over K=1024.
// c[mt][nt][4] per-thread accumulators. 8 warps: warpM=wid>>2 (x64 rows),
// warpN=wid&3 (x32 cols).
// ---------------------------------------------------------------------------
__device__ __forceinline__ void mma_mainloop(
    const float* __restrict__ A, const float* __restrict__ Bmat,
    int m0, int n0, uint32_t* As, uint32_t* Bs, float c[4][4][4])
{
    const int tid  = threadIdx.x;
    const int wid  = tid >> 5, lane = tid & 31;
    const int g    = lane >> 2, tg = lane & 3;
    const int warpM = wid >> 2, warpN = wid & 3;

#pragma unroll
    for (int mt = 0; mt < 4; mt++)
#pragma unroll
        for (int nt = 0; nt < 4; nt++)
#pragma unroll
            for (int r = 0; r < 4; r++) c[mt][nt][r] = 0.f;

    for (int kt = 0; kt < 32; kt++) {
        const int k0 = kt * 32;
        __syncthreads();
        // copy A,B k-slices to smem with tf32 rounding
        const float* Ag = A    + (size_t)m0 * 1024 + k0;
        const float* Bg = Bmat + (size_t)n0 * 1024 + k0;
#pragma unroll
        for (int j = 0; j < 4; j++) {
            int f   = tid * 4 + j;          // 0..1023 float4s
            int row = f >> 3;
            int cw  = (f & 7) * 4;          // word col 0..28
            float4 va = *(const float4*)(Ag + (size_t)row * 1024 + cw);
            float4 vb = *(const float4*)(Bg + (size_t)row * 1024 + cw);
            uint4 ua = make_uint4(f2tf32(va.x), f2tf32(va.y), f2tf32(va.z), f2tf32(va.w));
            uint4 ub = make_uint4(f2tf32(vb.x), f2tf32(vb.y), f2tf32(vb.z), f2tf32(vb.w));
            *(uint4*)&As[row * TSTR + cw] = ua;
            *(uint4*)&Bs[row * TSTR + cw] = ub;
        }
        __syncthreads();

#pragma unroll
        for (int ks = 0; ks < 4; ks++) {
            const int kk = ks * 8;
            uint32_t a[4][4], b[4][2];
#pragma unroll
            for (int mt = 0; mt < 4; mt++) {
                int r = warpM * 64 + mt * 16 + g;
                a[mt][0] = As[r * TSTR + kk + tg];
                a[mt][1] = As[(r + 8) * TSTR + kk + tg];
                a[mt][2] = As[r * TSTR + kk + tg + 4];
                a[mt][3] = As[(r + 8) * TSTR + kk + tg + 4];
            }
#pragma unroll
            for (int nt = 0; nt < 4; nt++) {
                int n = warpN * 32 + nt * 8 + g;
                b[nt][0] = Bs[n * TSTR + kk + tg];
                b[nt][1] = Bs[n * TSTR + kk + tg + 4];
            }
#pragma unroll
            for (int mt = 0; mt < 4; mt++)
#pragma unroll
                for (int nt = 0; nt < 4; nt++)
                    mma168(c[mt][nt], a[mt], b[nt]);
        }
    }
}

// ---------------------------------------------------------------------------
// Kernel 1: QKV GEMM (tf32 mma) + fused RoPE + scatter.
// grid = (24, 32), block = 256
// ---------------------------------------------------------------------------
__global__ __launch_bounds__(256, 2) void qkv_mma_kernel(
    const float* __restrict__ A,    // [4096][1024]
    const float* __restrict__ W,    // [3072][1024]
    const float* __restrict__ fr,   // [2048][128]
    const float* __restrict__ fi)
{
    __shared__ uint32_t As[128 * TSTR];
    __shared__ uint32_t Bs[128 * TSTR];
    const int tid  = threadIdx.x;
    const int wid  = tid >> 5, lane = tid & 31;
    const int g    = lane >> 2, tg = lane & 3;
    const int warpM = wid >> 2, warpN = wid & 3;
    const int m0 = blockIdx.y * 128;
    const int n0 = blockIdx.x * 128;

    float c[4][4][4];
    mma_mainloop(A, W, m0, n0, As, Bs, c);

    const int which = n0 >> 10;      // 0=q 1=k 2=v (tile never straddles)
#pragma unroll
    for (int mt = 0; mt < 4; mt++) {
#pragma unroll
        for (int half = 0; half < 2; half++) {
            int m  = m0 + warpM * 64 + mt * 16 + g + half * 8;
            int bb = m >> 11;
            int ss = m & 2047;
#pragma unroll
            for (int nt = 0; nt < 4; nt++) {
                int n = n0 + warpN * 32 + nt * 8 + tg * 2;
                int h = (n >> 8) & 3;
                int d = n & 255;
                float x0 = c[mt][nt][half * 2];
                float x1 = c[mt][nt][half * 2 + 1];
                size_t oidx = (((size_t)(bb * NHH + h)) * SS + ss) * HDD + d;
                if (which == 2) {
                    *(float2*)&g_v[oidx] = make_float2(x0, x1);
                } else {
                    float fre = __ldg(&fr[(size_t)ss * 128 + (d >> 1)]);
                    float fim = __ldg(&fi[(size_t)ss * 128 + (d >> 1)]);
                    float o0 = x0 * fre - x1 * fim;
                    float o1 = x0 * fim + x1 * fre;
                    float* dst = (which == 0) ? g_q : g_k;
                    *(float2*)&dst[oidx] = make_float2(o0, o1);
                }
            }
        }
    }
}

// ---------------------------------------------------------------------------
// Kernel 3: output GEMM (tf32 mma). grid = (8, 32), block = 256
// ---------------------------------------------------------------------------
__global__ __launch_bounds__(256, 2) void o_mma_kernel(
    const float* __restrict__ A,    // [4096][1024]
    const float* __restrict__ W,    // [1024][1024]
    float* __restrict__ C)          // [4096][1024]
{
    __shared__ uint32_t As[128 * TSTR];
    __shared__ uint32_t Bs[128 * TSTR];
    const int tid  = threadIdx.x;
    const int wid  = tid >> 5, lane = tid & 31;
    const int g    = lane >> 2, tg = lane & 3;
    const int warpM = wid >> 2, warpN = wid & 3;
    const int m0 = blockIdx.y * 128;
    const int n0 = blockIdx.x * 128;

    float c[4][4][4];
    mma_mainloop(A, W, m0, n0, As, Bs, c);

#pragma unroll
    for (int mt = 0; mt < 4; mt++) {
#pragma unroll
        for (int half = 0; half < 2; half++) {
            int m = m0 + warpM * 64 + mt * 16 + g + half * 8;
#pragma unroll
            for (int nt = 0; nt < 4; nt++) {
                int n = n0 + warpN * 32 + nt * 8 + tg * 2;
                *(float2*)&C[(size_t)m * 1024 + n] =
                    make_float2(c[mt][nt][half * 2], c[mt][nt][half * 2 + 1]);
            }
        }
    }
}

// ---------------------------------------------------------------------------
// Kernel 2: causal flash attention (unchanged from R2 — fp32 FFMA).
// ---------------------------------------------------------------------------
#define KSTR 68
#define PSTR 65

extern __shared__ float asmem[];

__global__ __launch_bounds__(256, 1) void attn_kernel(
    const float* __restrict__ qg, const float* __restrict__ kg,
    const float* __restrict__ vg, float* __restrict__ og)
{
    float* Qt = asmem;                 // [256][KSTR]  k-major
    float* Kt = Qt + 256 * KSTR;       // [256][KSTR]  k-major
    float* Vs = Kt + 256 * KSTR;       // [64][256]    row-major
    float* Ps = Vs + 64 * 256;         // [64][PSTR]
    float* rS = Ps + 64 * PSTR;        // [64]
    float* lS = rS + 64;               // [64]

    const int tid = threadIdx.x;
    const int nq  = gridDim.x;
    const int qt  = nq - 1 - blockIdx.x;
    const int q0  = qt * 64;
    const int h   = blockIdx.y;
    const int b   = blockIdx.z;
    const size_t base = ((size_t)(b * NHH + h)) * SS * HDD;
    const float scale = 0.0625f;

    {
        const float* qrow = qg + base + (size_t)q0 * HDD + tid;
        float* qdst = Qt + tid * KSTR;
#pragma unroll 4
        for (int r = 0; r < 64; r++)
            qdst[r] = qrow[(size_t)r * HDD] * scale;
    }

    const int r0 = (tid >> 4) * 4;
    const int c0 = (tid & 15) * 4;
    const int rp0 = (tid >> 5) * 8;
    const int cpA = (tid & 31) * 4;

    float mrun[4], lrun[4];
#pragma unroll
    for (int i = 0; i < 4; i++) { mrun[i] = -1e30f; lrun[i] = 0.f; }

    float o[8][8];
#pragma unroll
    for (int i = 0; i < 8; i++)
#pragma unroll
        for (int cc = 0; cc < 8; cc++) o[i][cc] = 0.f;

    const int nkb = qt + 1;
    for (int kbi = 0; kbi < nkb; kbi++) {
        const int k0 = kbi * 64;
        __syncthreads();

        {
            const float* krow = kg + base + (size_t)k0 * HDD + tid;
            float* kdst = Kt + tid * KSTR;
#pragma unroll 4
            for (int r = 0; r < 64; r++)
                kdst[r] = krow[(size_t)r * HDD];
        }
        {
            int r = tid >> 2, c4 = (tid & 3) * 4;
#pragma unroll
            for (int it = 0; it < 16; it++) {
                *(float4*)&Vs[r * 256 + c4 + it * 16] =
                    *(const float4*)&vg[base + (size_t)(k0 + r) * HDD + c4 + it * 16];
            }
        }
        __syncthreads();

        float sacc[4][4];
#pragma unroll
        for (int i = 0; i < 4; i++)
#pragma unroll
            for (int j = 0; j < 4; j++) sacc[i][j] = 0.f;

#pragma unroll 4
        for (int kk = 0; kk < 256; kk++) {
            float4 a  = *(const float4*)&Qt[kk * KSTR + r0];
            float4 bq = *(const float4*)&Kt[kk * KSTR + c0];
            sacc[0][0] += a.x * bq.x; sacc[0][1] += a.x * bq.y;
            sacc[0][2] += a.x * bq.z; sacc[0][3] += a.x * bq.w;
            sacc[1][0] += a.y * bq.x; sacc[1][1] += a.y * bq.y;
            sacc[1][2] += a.y * bq.z; sacc[1][3] += a.y * bq.w;
            sacc[2][0] += a.z * bq.x; sacc[2][1] += a.z * bq.y;
            sacc[2][2] += a.z * bq.z; sacc[2][3] += a.z * bq.w;
            sacc[3][0] += a.w * bq.x; sacc[3][1] += a.w * bq.y;
            sacc[3][2] += a.w * bq.z; sacc[3][3] += a.w * bq.w;
        }

        float resc[4];
#pragma unroll
        for (int i = 0; i < 4; i++) {
            int qi = q0 + r0 + i;
            float mx = -1e30f;
#pragma unroll
            for (int j = 0; j < 4; j++) {
                if (k0 + c0 + j > qi) sacc[i][j] = -1e30f;
                mx = fmaxf(mx, sacc[i][j]);
            }
            mx = fmaxf(mx, __shfl_xor_sync(0xffffffffu, mx, 1));
            mx = fmaxf(mx, __shfl_xor_sync(0xffffffffu, mx, 2));
            mx = fmaxf(mx, __shfl_xor_sync(0xffffffffu, mx, 4));
            mx = fmaxf(mx, __shfl_xor_sync(0xffffffffu, mx, 8));
            float mnew = fmaxf(mrun[i], mx);
            resc[i] = __expf(mrun[i] - mnew);
            float sum = 0.f;
#pragma unroll
            for (int j = 0; j < 4; j++) {
                float p = __expf(sacc[i][j] - mnew);
                Ps[(r0 + i) * PSTR + c0 + j] = p;
                sum += p;
            }
            sum += __shfl_xor_sync(0xffffffffu, sum, 1);
            sum += __shfl_xor_sync(0xffffffffu, sum, 2);
            sum += __shfl_xor_sync(0xffffffffu, sum, 4);
            sum += __shfl_xor_sync(0xffffffffu, sum, 8);
            lrun[i] = lrun[i] * resc[i] + sum;
            mrun[i] = mnew;
        }
        if ((tid & 15) == 0) {
#pragma unroll
            for (int i = 0; i < 4; i++) rS[r0 + i] = resc[i];
        }
        __syncthreads();

        float rr[8];
#pragma unroll
        for (int i = 0; i < 8; i++) rr[i] = rS[rp0 + i];
#pragma unroll
        for (int i = 0; i < 8; i++)
#pragma unroll
            for (int cc = 0; cc < 8; cc++) o[i][cc] *= rr[i];

#pragma unroll 2
        for (int j = 0; j < 64; j++) {
            float4 v0 = *(const float4*)&Vs[j * 256 + cpA];
            float4 v1 = *(const float4*)&Vs[j * 256 + cpA + 128];
#pragma unroll
            for (int i = 0; i < 8; i++) {
                float p = Ps[(rp0 + i) * PSTR + j];
                o[i][0] += p * v0.x; o[i][1] += p * v0.y;
                o[i][2] += p * v0.z; o[i][3] += p * v0.w;
                o[i][4] += p * v1.x; o[i][5] += p * v1.y;
                o[i][6] += p * v1.z; o[i][7] += p * v1.w;
            }
        }
    }

    if ((tid & 15) == 0) {
#pragma unroll
        for (int i = 0; i < 4; i++) lS[r0 + i] = 1.f / lrun[i];
    }
    __syncthreads();

#pragma unroll
    for (int i = 0; i < 8; i++) {
        float linv = lS[rp0 + i];
        size_t ob = ((size_t)b * SS + (q0 + rp0 + i)) * HIDD + h * HDD;
        float4 w0 = make_float4(o[i][0] * linv, o[i][1] * linv,
                                o[i][2] * linv, o[i][3] * linv);
        float4 w1 = make_float4(o[i][4] * linv, o[i][5] * linv,
                                o[i][6] * linv, o[i][7] * linv);
        *(float4*)&og[ob + cpA]       = w0;
        *(float4*)&og[ob + cpA + 128] = w1;
    }
}

// ---------------------------------------------------------------------------
extern "C" void kernel_launch(void* const* d_in, const int* in_sizes, int n_in,
                              void* d_out, int out_size)
{
    const float* hidden = (const float*)d_in[0];
    const float* fr     = (const float*)d_in[1];
    const float* fi     = (const float*)d_in[2];
    // d_in[3] = mask (causal handled analytically)
    const float* Wqkv   = (const float*)d_in[4];
    const float* Wo     = (const float*)d_in[5];
    float* out = (float*)d_out;

    float *qb, *kb, *vb, *ob;
    cudaGetSymbolAddress((void**)&qb, g_q);
    cudaGetSymbolAddress((void**)&kb, g_k);
    cudaGetSymbolAddress((void**)&vb, g_v);
    cudaGetSymbolAddress((void**)&ob, g_o);

    // 1) QKV + RoPE on tf32 mma.sync
    dim3 g1(3072 / 128, 4096 / 128);
    qkv_mma_kernel<<<g1, 256>>>(hidden, Wqkv, fr, fi);

    // 2) flash attention
    const int smem = (2 * 256 * KSTR + 64 * 256 + 64 * PSTR + 128) * (int)sizeof(float);
    cudaFuncSetAttribute(attn_kernel, cudaFuncAttributeMaxDynamicSharedMemorySize, smem);
    dim3 g2(SS / 64, NHH, BB);
    attn_kernel<<<g2, 256, smem>>>(qb, kb, vb, ob);

    // 3) output projection on tf32 mma.sync
    dim3 g3(1024 / 128, 4096 / 128);
    o_mma_kernel<<<g3, 256>>>(ob, Wo, out);
}

// round 6
// speedup vs baseline: 8.9536x; 1.9252x over previous
#include <cuda_runtime.h>
#include <cstdint>

#define BB   2
#define SS   2048
#define HIDD 1024
#define NHH  4
#define HDD  256

// Scratch (allocation-free rule -> __device__ globals)
__device__ float g_q[BB*NHH*SS*HDD];
__device__ float g_k[BB*NHH*SS*HDD];
__device__ float g_v[BB*NHH*SS*HDD];
__device__ float g_o[BB*SS*HIDD];

// ---------------------------------------------------------------------------
// tf32 mma.sync helpers (base PTX ISA, works on sm_103 target)
// ---------------------------------------------------------------------------
__device__ __forceinline__ void mma168(float* c, const uint32_t* a, const uint32_t* b) {
    asm volatile(
        "mma.sync.aligned.m16n8k8.row.col.f32.tf32.tf32.f32 "
        "{%0,%1,%2,%3}, {%4,%5,%6,%7}, {%8,%9}, {%0,%1,%2,%3};"
        : "+f"(c[0]), "+f"(c[1]), "+f"(c[2]), "+f"(c[3])
        : "r"(a[0]), "r"(a[1]), "r"(a[2]), "r"(a[3]), "r"(b[0]), "r"(b[1]));
}
__device__ __forceinline__ uint32_t f2tf32(float x) {
    uint32_t u;
    asm("cvt.rna.tf32.f32 %0, %1;" : "=r"(u) : "f"(x));
    return u;
}

// ===========================================================================
// GEMM kernels (unchanged from R4)
// ===========================================================================
#define TSTR 36

__device__ __forceinline__ void mma_mainloop(
    const float* __restrict__ A, const float* __restrict__ Bmat,
    int m0, int n0, uint32_t* As, uint32_t* Bs, float c[4][4][4])
{
    const int tid  = threadIdx.x;
    const int wid  = tid >> 5, lane = tid & 31;
    const int g    = lane >> 2, tg = lane & 3;
    const int warpM = wid >> 2, warpN = wid & 3;

#pragma unroll
    for (int mt = 0; mt < 4; mt++)
#pragma unroll
        for (int nt = 0; nt < 4; nt++)
#pragma unroll
            for (int r = 0; r < 4; r++) c[mt][nt][r] = 0.f;

    for (int kt = 0; kt < 32; kt++) {
        const int k0 = kt * 32;
        __syncthreads();
        const float* Ag = A    + (size_t)m0 * 1024 + k0;
        const float* Bg = Bmat + (size_t)n0 * 1024 + k0;
#pragma unroll
        for (int j = 0; j < 4; j++) {
            int f   = tid * 4 + j;
            int row = f >> 3;
            int cw  = (f & 7) * 4;
            float4 va = *(const float4*)(Ag + (size_t)row * 1024 + cw);
            float4 vb = *(const float4*)(Bg + (size_t)row * 1024 + cw);
            uint4 ua = make_uint4(f2tf32(va.x), f2tf32(va.y), f2tf32(va.z), f2tf32(va.w));
            uint4 ub = make_uint4(f2tf32(vb.x), f2tf32(vb.y), f2tf32(vb.z), f2tf32(vb.w));
            *(uint4*)&As[row * TSTR + cw] = ua;
            *(uint4*)&Bs[row * TSTR + cw] = ub;
        }
        __syncthreads();

#pragma unroll
        for (int ks = 0; ks < 4; ks++) {
            const int kk = ks * 8;
            uint32_t a[4][4], b[4][2];
#pragma unroll
            for (int mt = 0; mt < 4; mt++) {
                int r = warpM * 64 + mt * 16 + g;
                a[mt][0] = As[r * TSTR + kk + tg];
                a[mt][1] = As[(r + 8) * TSTR + kk + tg];
                a[mt][2] = As[r * TSTR + kk + tg + 4];
                a[mt][3] = As[(r + 8) * TSTR + kk + tg + 4];
            }
#pragma unroll
            for (int nt = 0; nt < 4; nt++) {
                int n = warpN * 32 + nt * 8 + g;
                b[nt][0] = Bs[n * TSTR + kk + tg];
                b[nt][1] = Bs[n * TSTR + kk + tg + 4];
            }
#pragma unroll
            for (int mt = 0; mt < 4; mt++)
#pragma unroll
                for (int nt = 0; nt < 4; nt++)
                    mma168(c[mt][nt], a[mt], b[nt]);
        }
    }
}

__global__ __launch_bounds__(256, 2) void qkv_mma_kernel(
    const float* __restrict__ A, const float* __restrict__ W,
    const float* __restrict__ fr, const float* __restrict__ fi)
{
    __shared__ uint32_t As[128 * TSTR];
    __shared__ uint32_t Bs[128 * TSTR];
    const int tid  = threadIdx.x;
    const int wid  = tid >> 5, lane = tid & 31;
    const int g    = lane >> 2, tg = lane & 3;
    const int warpM = wid >> 2, warpN = wid & 3;
    const int m0 = blockIdx.y * 128;
    const int n0 = blockIdx.x * 128;

    float c[4][4][4];
    mma_mainloop(A, W, m0, n0, As, Bs, c);

    const int which = n0 >> 10;
#pragma unroll
    for (int mt = 0; mt < 4; mt++) {
#pragma unroll
        for (int half = 0; half < 2; half++) {
            int m  = m0 + warpM * 64 + mt * 16 + g + half * 8;
            int bb = m >> 11;
            int ss = m & 2047;
#pragma unroll
            for (int nt = 0; nt < 4; nt++) {
                int n = n0 + warpN * 32 + nt * 8 + tg * 2;
                int h = (n >> 8) & 3;
                int d = n & 255;
                float x0 = c[mt][nt][half * 2];
                float x1 = c[mt][nt][half * 2 + 1];
                size_t oidx = (((size_t)(bb * NHH + h)) * SS + ss) * HDD + d;
                if (which == 2) {
                    *(float2*)&g_v[oidx] = make_float2(x0, x1);
                } else {
                    float fre = __ldg(&fr[(size_t)ss * 128 + (d >> 1)]);
                    float fim = __ldg(&fi[(size_t)ss * 128 + (d >> 1)]);
                    float o0 = x0 * fre - x1 * fim;
                    float o1 = x0 * fim + x1 * fre;
                    float* dst = (which == 0) ? g_q : g_k;
                    *(float2*)&dst[oidx] = make_float2(o0, o1);
                }
            }
        }
    }
}

__global__ __launch_bounds__(256, 2) void o_mma_kernel(
    const float* __restrict__ A, const float* __restrict__ W,
    float* __restrict__ C)
{
    __shared__ uint32_t As[128 * TSTR];
    __shared__ uint32_t Bs[128 * TSTR];
    const int tid  = threadIdx.x;
    const int wid  = tid >> 5, lane = tid & 31;
    const int g    = lane >> 2, tg = lane & 3;
    const int warpM = wid >> 2, warpN = wid & 3;
    const int m0 = blockIdx.y * 128;
    const int n0 = blockIdx.x * 128;

    float c[4][4][4];
    mma_mainloop(A, W, m0, n0, As, Bs, c);

#pragma unroll
    for (int mt = 0; mt < 4; mt++) {
#pragma unroll
        for (int half = 0; half < 2; half++) {
            int m = m0 + warpM * 64 + mt * 16 + g + half * 8;
#pragma unroll
            for (int nt = 0; nt < 4; nt++) {
                int n = n0 + warpN * 32 + nt * 8 + tg * 2;
                *(float2*)&C[(size_t)m * 1024 + n] =
                    make_float2(c[mt][nt][half * 2], c[mt][nt][half * 2 + 1]);
            }
        }
    }
}

// ===========================================================================
// Kernel 2: tensor-core causal flash attention (tf32 mma.sync).
// CTA: 64 q-rows. 8 warps. K/V tiles of 64 rows.
// S phase : warps (4 row-slabs x 16) x (2 col-halves x 32)
// PV phase: warps (4 row-slabs x 16) x (2 col-halves x 128)
// ===========================================================================
#define QSTR 260
#define VSTR 260
#define PSTR 68

extern __shared__ uint32_t attn_sm[];

__global__ __launch_bounds__(256, 1) void attn_mma_kernel(
    const float* __restrict__ qg, const float* __restrict__ kg,
    const float* __restrict__ vg, float* __restrict__ og)
{
    uint32_t* Qs = attn_sm;                 // [64][QSTR] tf32
    uint32_t* Ks = Qs + 64 * QSTR;          // [64][QSTR] tf32
    uint32_t* Vs = Ks + 64 * QSTR;          // [64][VSTR] tf32
    uint32_t* Ps = Vs + 64 * VSTR;          // [64][PSTR] tf32
    float* mS   = (float*)(Ps + 64 * PSTR); // [64]
    float* lS   = mS + 64;                  // [64]
    float* pmax = lS + 64;                  // [2][64]
    float* psum = pmax + 128;               // [2][64]

    const int tid  = threadIdx.x;
    const int wid  = tid >> 5, lane = tid & 31;
    const int g    = lane >> 2, tg = lane & 3;
    const int warpRow = wid >> 1;           // 0..3 : rows warpRow*16 ..+15
    const int warpCol = wid & 1;            // 0..1

    const int qt  = gridDim.x - 1 - blockIdx.x;   // heavy CTAs first
    const int q0  = qt * 64;
    const int h   = blockIdx.y;
    const int b   = blockIdx.z;
    const size_t base = ((size_t)(b * NHH + h)) * SS * HDD;
    const float scale = 0.0625f;

    // load Q tile (scaled, tf32)
#pragma unroll
    for (int it = 0; it < 16; it++) {
        int f   = tid + it * 256;
        int row = f >> 6;
        int c4  = (f & 63) * 4;
        float4 v = *(const float4*)&qg[base + (size_t)(q0 + row) * HDD + c4];
        *(uint4*)&Qs[row * QSTR + c4] =
            make_uint4(f2tf32(v.x * scale), f2tf32(v.y * scale),
                       f2tf32(v.z * scale), f2tf32(v.w * scale));
    }
    if (tid < 64) { mS[tid] = -1e30f; lS[tid] = 0.f; }

    float o[16][4];
#pragma unroll
    for (int nt = 0; nt < 16; nt++)
#pragma unroll
        for (int r = 0; r < 4; r++) o[nt][r] = 0.f;

    const int rg = warpRow * 16 + g;        // first row this lane owns

    const int nkb = qt + 1;
    for (int kbi = 0; kbi < nkb; kbi++) {
        const int k0 = kbi * 64;
        __syncthreads();                    // prev PV done with Vs/Ps

        // load K,V tiles (tf32)
#pragma unroll
        for (int it = 0; it < 16; it++) {
            int f   = tid + it * 256;
            int row = f >> 6;
            int c4  = (f & 63) * 4;
            size_t gi = base + (size_t)(k0 + row) * HDD + c4;
            float4 kv = *(const float4*)&kg[gi];
            float4 vv = *(const float4*)&vg[gi];
            *(uint4*)&Ks[row * QSTR + c4] =
                make_uint4(f2tf32(kv.x), f2tf32(kv.y), f2tf32(kv.z), f2tf32(kv.w));
            *(uint4*)&Vs[row * VSTR + c4] =
                make_uint4(f2tf32(vv.x), f2tf32(vv.y), f2tf32(vv.z), f2tf32(vv.w));
        }
        __syncthreads();

        // ---- S = Q K^T : warp tile 16 x 32 ----
        float s[4][4];
#pragma unroll
        for (int nt = 0; nt < 4; nt++)
#pragma unroll
            for (int r = 0; r < 4; r++) s[nt][r] = 0.f;

#pragma unroll 4
        for (int kk = 0; kk < 256; kk += 8) {
            uint32_t a[4];
            a[0] = Qs[rg * QSTR + kk + tg];
            a[1] = Qs[(rg + 8) * QSTR + kk + tg];
            a[2] = Qs[rg * QSTR + kk + tg + 4];
            a[3] = Qs[(rg + 8) * QSTR + kk + tg + 4];
#pragma unroll
            for (int nt = 0; nt < 4; nt++) {
                int n = warpCol * 32 + nt * 8 + g;
                uint32_t bb2[2];
                bb2[0] = Ks[n * QSTR + kk + tg];
                bb2[1] = Ks[n * QSTR + kk + tg + 4];
                mma168(s[nt], a, bb2);
            }
        }

        // causal mask on diagonal tile
        if (kbi == qt) {
#pragma unroll
            for (int nt = 0; nt < 4; nt++) {
#pragma unroll
                for (int r = 0; r < 4; r++) {
                    int row = q0 + rg + ((r & 2) ? 8 : 0);
                    int col = k0 + warpCol * 32 + nt * 8 + 2 * tg + (r & 1);
                    if (col > row) s[nt][r] = -1e30f;
                }
            }
        }

        // partial row max (rows rg, rg+8) within this warp's 32 cols
        float mx0 = -1e30f, mx1 = -1e30f;
#pragma unroll
        for (int nt = 0; nt < 4; nt++) {
            mx0 = fmaxf(mx0, fmaxf(s[nt][0], s[nt][1]));
            mx1 = fmaxf(mx1, fmaxf(s[nt][2], s[nt][3]));
        }
        mx0 = fmaxf(mx0, __shfl_xor_sync(0xffffffffu, mx0, 1));
        mx0 = fmaxf(mx0, __shfl_xor_sync(0xffffffffu, mx0, 2));
        mx1 = fmaxf(mx1, __shfl_xor_sync(0xffffffffu, mx1, 1));
        mx1 = fmaxf(mx1, __shfl_xor_sync(0xffffffffu, mx1, 2));
        if (tg == 0) {
            pmax[warpCol * 64 + rg]     = mx0;
            pmax[warpCol * 64 + rg + 8] = mx1;
        }
        __syncthreads();

        float m0old = mS[rg], m1old = mS[rg + 8];
        float m0 = fmaxf(m0old, fmaxf(pmax[rg],     pmax[64 + rg]));
        float m1 = fmaxf(m1old, fmaxf(pmax[rg + 8], pmax[64 + rg + 8]));
        float resc0 = __expf(m0old - m0);
        float resc1 = __expf(m1old - m1);

        float sum0 = 0.f, sum1 = 0.f;
#pragma unroll
        for (int nt = 0; nt < 4; nt++) {
            int cl = warpCol * 32 + nt * 8 + 2 * tg;
            float p0 = __expf(s[nt][0] - m0);
            float p1 = __expf(s[nt][1] - m0);
            float p2 = __expf(s[nt][2] - m1);
            float p3 = __expf(s[nt][3] - m1);
            sum0 += p0 + p1;
            sum1 += p2 + p3;
            Ps[rg * PSTR + cl]           = f2tf32(p0);
            Ps[rg * PSTR + cl + 1]       = f2tf32(p1);
            Ps[(rg + 8) * PSTR + cl]     = f2tf32(p2);
            Ps[(rg + 8) * PSTR + cl + 1] = f2tf32(p3);
        }
        sum0 += __shfl_xor_sync(0xffffffffu, sum0, 1);
        sum0 += __shfl_xor_sync(0xffffffffu, sum0, 2);
        sum1 += __shfl_xor_sync(0xffffffffu, sum1, 1);
        sum1 += __shfl_xor_sync(0xffffffffu, sum1, 2);
        if (tg == 0) {
            psum[warpCol * 64 + rg]     = sum0;
            psum[warpCol * 64 + rg + 8] = sum1;
        }
        __syncthreads();

        // stats update (one owner per row)
        if (warpCol == 0 && tg == 0) {
            lS[rg]     = lS[rg]     * resc0 + psum[rg]     + psum[64 + rg];
            lS[rg + 8] = lS[rg + 8] * resc1 + psum[rg + 8] + psum[64 + rg + 8];
            mS[rg]     = m0;
            mS[rg + 8] = m1;
        }

        // ---- O = O*resc + P V : warp tile 16 x 128 ----
#pragma unroll
        for (int nt = 0; nt < 16; nt++) {
            o[nt][0] *= resc0; o[nt][1] *= resc0;
            o[nt][2] *= resc1; o[nt][3] *= resc1;
        }
#pragma unroll
        for (int kk8 = 0; kk8 < 8; kk8++) {
            const int kk = kk8 * 8;
            uint32_t a[4];
            a[0] = Ps[rg * PSTR + kk + tg];
            a[1] = Ps[(rg + 8) * PSTR + kk + tg];
            a[2] = Ps[rg * PSTR + kk + tg + 4];
            a[3] = Ps[(rg + 8) * PSTR + kk + tg + 4];
#pragma unroll
            for (int nt = 0; nt < 16; nt++) {
                int n = warpCol * 128 + nt * 8 + g;
                uint32_t bb2[2];
                bb2[0] = Vs[(kk + tg) * VSTR + n];
                bb2[1] = Vs[(kk + tg + 4) * VSTR + n];
                mma168(o[nt], a, bb2);
            }
        }
    }
    __syncthreads();

    // epilogue: normalize + write
    float linv0 = 1.f / lS[rg];
    float linv1 = 1.f / lS[rg + 8];
    size_t ob0 = ((size_t)b * SS + (q0 + rg))     * HIDD + h * HDD;
    size_t ob1 = ((size_t)b * SS + (q0 + rg + 8)) * HIDD + h * HDD;
#pragma unroll
    for (int nt = 0; nt < 16; nt++) {
        int col = warpCol * 128 + nt * 8 + 2 * tg;
        *(float2*)&og[ob0 + col] = make_float2(o[nt][0] * linv0, o[nt][1] * linv0);
        *(float2*)&og[ob1 + col] = make_float2(o[nt][2] * linv1, o[nt][3] * linv1);
    }
}

// ---------------------------------------------------------------------------
extern "C" void kernel_launch(void* const* d_in, const int* in_sizes, int n_in,
                              void* d_out, int out_size)
{
    const float* hidden = (const float*)d_in[0];
    const float* fr     = (const float*)d_in[1];
    const float* fi     = (const float*)d_in[2];
    // d_in[3] = mask (causal handled analytically)
    const float* Wqkv   = (const float*)d_in[4];
    const float* Wo     = (const float*)d_in[5];
    float* out = (float*)d_out;

    float *qb, *kb, *vb, *ob;
    cudaGetSymbolAddress((void**)&qb, g_q);
    cudaGetSymbolAddress((void**)&kb, g_k);
    cudaGetSymbolAddress((void**)&vb, g_v);
    cudaGetSymbolAddress((void**)&ob, g_o);

    // 1) QKV + RoPE on tf32 mma.sync
    dim3 g1(3072 / 128, 4096 / 128);
    qkv_mma_kernel<<<g1, 256>>>(hidden, Wqkv, fr, fi);

    // 2) tensor-core flash attention
    const int asmB = (3 * 64 * QSTR + 64 * PSTR + 64 * 2 + 128 * 2) * 4;
    cudaFuncSetAttribute(attn_mma_kernel, cudaFuncAttributeMaxDynamicSharedMemorySize, asmB);
    dim3 g2(SS / 64, NHH, BB);
    attn_mma_kernel<<<g2, 256, asmB>>>(qb, kb, vb, ob);

    // 3) output projection on tf32 mma.sync
    dim3 g3(1024 / 128, 4096 / 128);
    o_mma_kernel<<<g3, 256>>>(ob, Wo, out);
}